// round 2
// baseline (speedup 1.0000x reference)
#include <cuda_runtime.h>
#include <math.h>

// ArcFace fused loss. N=512, D=512, C=100000.
// Pipeline:
//   1) norm_x:   x_hat = x / max(||x||, 1e-12)   (also zeroes per-row sum accumulators)
//   2) wnorm:    rnorm_c = 1 / max(||w_c||, 1e-12)
//   3) gemm:     128x128 fp32 SIMT tile GEMM over K=512, epilogue applies
//                clip/margin and accumulates sum_c exp(logit - 64) per row +
//                records the target logit.
//   4) finalize: mean_i [ log(rowsum_i) + 64 - target_logit_i ]  -> d_out[0]

#define N_ 512
#define D_ 512
#define C_ 100000

#define SCALE_   64.0f
#define CLIP_LO  (-1.0f + 1e-7f)
#define CLIP_HI  (1.0f - 1e-7f)
#define COS_M_   0.8775825618903728f   // cos(0.5)
#define SIN_M_   0.4794255386042030f   // sin(0.5)
#define TH_      (-0.8775825618903728f) // cos(pi - 0.5)
#define MM_      0.2397127693021015f   // sin(pi - 0.5) * 0.5

__device__ float g_xn[N_ * D_];     // normalized input
__device__ float g_wrn[C_];         // 1/||w_c||
__device__ float g_rowsum[N_];      // sum_c exp(logit - 64)
__device__ float g_tlogit[N_];      // target logit per row

// ---------------------------------------------------------------------------
// 1) normalize input rows; zero row sums
// ---------------------------------------------------------------------------
__global__ void norm_x_kernel(const float* __restrict__ x) {
    int row = blockIdx.x;            // 512 blocks
    int tid = threadIdx.x;           // 128 threads, 4 floats each
    if (tid == 0) g_rowsum[row] = 0.0f;

    float4 v = *(const float4*)(x + (size_t)row * D_ + tid * 4);
    float ss = v.x * v.x + v.y * v.y + v.z * v.z + v.w * v.w;
    #pragma unroll
    for (int o = 16; o; o >>= 1) ss += __shfl_xor_sync(0xffffffffu, ss, o);

    __shared__ float sm[4];
    if ((tid & 31) == 0) sm[tid >> 5] = ss;
    __syncthreads();
    float tot = sm[0] + sm[1] + sm[2] + sm[3];
    float inv = 1.0f / fmaxf(sqrtf(tot), 1e-12f);

    float4 o4;
    o4.x = v.x * inv; o4.y = v.y * inv; o4.z = v.z * inv; o4.w = v.w * inv;
    *(float4*)(g_xn + (size_t)row * D_ + tid * 4) = o4;
}

// ---------------------------------------------------------------------------
// 2) weight row inverse norms (one warp per class row)
// ---------------------------------------------------------------------------
__global__ void wnorm_kernel(const float* __restrict__ w, int C) {
    int warp = (blockIdx.x * blockDim.x + threadIdx.x) >> 5;
    int lane = threadIdx.x & 31;
    if (warp >= C) return;
    const float* p = w + (size_t)warp * D_;
    float ss = 0.0f;
    #pragma unroll
    for (int q = 0; q < 4; q++) {
        float4 v = *(const float4*)(p + lane * 4 + q * 128);
        ss += v.x * v.x + v.y * v.y + v.z * v.z + v.w * v.w;
    }
    #pragma unroll
    for (int o = 16; o; o >>= 1) ss += __shfl_xor_sync(0xffffffffu, ss, o);
    if (lane == 0) g_wrn[warp] = 1.0f / fmaxf(sqrtf(ss), 1e-12f);
}

// ---------------------------------------------------------------------------
// 3) tiled GEMM + ArcFace epilogue + online sum-of-exp
//    BM=128 (rows of x), BN=128 (classes), BK=16, 256 threads, 8x8/thread
// ---------------------------------------------------------------------------
__global__ void __launch_bounds__(256, 2)
arcface_gemm_kernel(const float* __restrict__ w,
                    const int* __restrict__ target, int C) {
    __shared__ float As[16][132];   // [k][m], padded pitch to break store conflicts
    __shared__ float Bs[16][132];   // [k][n]

    int tid = threadIdx.x;
    int m0 = blockIdx.x * 128;      // grid.x = 4  (M-tiles adjacent -> weight tile L2 reuse)
    int c0 = blockIdx.y * 128;      // grid.y = 782
    int tx = tid & 15;
    int ty = tid >> 4;
    int lrow = tid >> 2;            // 0..63
    int lf   = tid & 3;             // which float4 along k

    float acc[8][8];
    #pragma unroll
    for (int i = 0; i < 8; i++)
        #pragma unroll
        for (int j = 0; j < 8; j++) acc[i][j] = 0.0f;

    for (int k0 = 0; k0 < D_; k0 += 16) {
        #pragma unroll
        for (int it = 0; it < 2; it++) {
            int r = lrow + it * 64;
            float4 av = *(const float4*)(g_xn + (size_t)(m0 + r) * D_ + k0 + lf * 4);
            As[lf * 4 + 0][r] = av.x;
            As[lf * 4 + 1][r] = av.y;
            As[lf * 4 + 2][r] = av.z;
            As[lf * 4 + 3][r] = av.w;

            int c = c0 + r;
            float4 bv = make_float4(0.f, 0.f, 0.f, 0.f);
            if (c < C)
                bv = *(const float4*)(w + (size_t)c * D_ + k0 + lf * 4);
            Bs[lf * 4 + 0][r] = bv.x;
            Bs[lf * 4 + 1][r] = bv.y;
            Bs[lf * 4 + 2][r] = bv.z;
            Bs[lf * 4 + 3][r] = bv.w;
        }
        __syncthreads();

        #pragma unroll
        for (int k = 0; k < 16; k++) {
            float a[8], b[8];
            *(float4*)&a[0] = *(const float4*)&As[k][ty * 4];
            *(float4*)&a[4] = *(const float4*)&As[k][64 + ty * 4];
            *(float4*)&b[0] = *(const float4*)&Bs[k][tx * 4];
            *(float4*)&b[4] = *(const float4*)&Bs[k][64 + tx * 4];
            #pragma unroll
            for (int i = 0; i < 8; i++)
                #pragma unroll
                for (int j = 0; j < 8; j++)
                    acc[i][j] += a[i] * b[j];
        }
        __syncthreads();
    }

    // --- epilogue: clip, margin on target column, sum exp(logit - 64) per row
    #pragma unroll
    for (int i = 0; i < 8; i++) {
        int rm = (i < 4) ? (ty * 4 + i) : (64 + ty * 4 + (i - 4));
        int gm = m0 + rm;
        int tgt = target[gm];
        float p = 0.0f;
        #pragma unroll
        for (int j = 0; j < 8; j++) {
            int cn = (j < 4) ? (tx * 4 + j) : (64 + tx * 4 + (j - 4));
            int gc = c0 + cn;
            if (gc < C) {
                float cosv = acc[i][j] * g_wrn[gc];
                cosv = fminf(fmaxf(cosv, CLIP_LO), CLIP_HI);
                float logit;
                if (gc == tgt) {
                    float t = 1.0f - cosv * cosv;
                    t = fminf(fmaxf(t, CLIP_LO), CLIP_HI);
                    float sine = sqrtf(t);
                    float phi = cosv * COS_M_ - sine * SIN_M_;
                    if (!(cosv > TH_)) phi = cosv - MM_;
                    logit = phi * SCALE_;
                    g_tlogit[gm] = logit;   // exactly one writer per row
                } else {
                    logit = cosv * SCALE_;
                }
                p += __expf(logit - 64.0f);
            }
        }
        // reduce across the 16 tx lanes (width-16 segments inside the warp)
        #pragma unroll
        for (int o = 8; o; o >>= 1)
            p += __shfl_down_sync(0xffffffffu, p, o, 16);
        if (tx == 0)
            atomicAdd(&g_rowsum[gm], p);
    }
}

// ---------------------------------------------------------------------------
// 4) finalize: mean NLL
// ---------------------------------------------------------------------------
__global__ void finalize_kernel(float* __restrict__ out) {
    int i = threadIdx.x;  // 512
    float v = (logf(g_rowsum[i]) + 64.0f) - g_tlogit[i];
    #pragma unroll
    for (int o = 16; o; o >>= 1) v += __shfl_xor_sync(0xffffffffu, v, o);
    __shared__ float sm[16];
    if ((i & 31) == 0) sm[i >> 5] = v;
    __syncthreads();
    if (i < 16) {
        float t = sm[i];
        #pragma unroll
        for (int o = 8; o; o >>= 1) t += __shfl_xor_sync(0x0000ffffu, t, o);
        if (i == 0) out[0] = t * (1.0f / (float)N_);
    }
}

// ---------------------------------------------------------------------------
extern "C" void kernel_launch(void* const* d_in, const int* in_sizes, int n_in,
                              void* d_out, int out_size) {
    const float* x   = (const float*)d_in[0];   // [512, 512] fp32
    const int*   tgt = (const int*)d_in[1];     // [512] (jax x64 off -> int32)
    const float* w   = (const float*)d_in[2];   // [100000, 512] fp32

    norm_x_kernel<<<N_, 128>>>(x);
    wnorm_kernel<<<(C_ + 7) / 8, 256>>>(w, C_);
    dim3 grid(4, (C_ + 127) / 128);
    arcface_gemm_kernel<<<grid, 256>>>(w, tgt, C_);
    finalize_kernel<<<1, N_>>>((float*)d_out);
}

// round 4
// speedup vs baseline: 3.1830x; 3.1830x over previous
#include <cuda_runtime.h>
#include <math.h>
#include <stdint.h>

// ArcFace fused loss, sm_103-base-target tensor cores (mma.sync tf32).
// N=512, D=512, C=100000.
//   norm_x  : x_hat rows -> g_xn, zero g_rowsum
//   gemm    : 128x128x32 cp.async double-buffered tiles, 8 warps x (64x32),
//             mma.sync.m16n8k8.tf32. Fused: per-class sum(w^2) from the live
//             B stage; epilogue applies clip + ArcFace margin on the target
//             column and accumulates exp(logit-64) row partials
//             (fixed-shift softmax: logits <= 64 always).
//   finalize: mean_i [log(rowsum_i) + 64 - tlogit_i] -> d_out[0]

#define N_ 512
#define D_ 512
#define C_ 100000
#define NCHUNK 16            // 512 / 32

#define SCALE_   64.0f
#define CLIP_LO  (-1.0f + 1e-7f)
#define CLIP_HI  (1.0f - 1e-7f)
#define COS_M_   0.8775825618903728f
#define SIN_M_   0.4794255386042030f
#define TH_      (-0.8775825618903728f)
#define MM_      0.2397127693021015f

// dynamic smem (floats):
//   As[2]: 128 rows x 36 (pitch) per stage -> 4608 floats/stage
//   Bs[2]: same
//   wrn  : 128 floats   rowacc: 128 floats
#define F_AS(s)   ((s) * 4608)
#define F_BS(s)   (9216 + (s) * 4608)
#define F_WRN     18432
#define F_ROW     18560
#define SMEM_BYTES (18688 * 4)

__device__ float g_xn[N_ * D_];
__device__ float g_rowsum[N_];
__device__ float g_tlogit[N_];

// ------------------------------------------------------------------ helpers
__device__ __forceinline__ uint32_t smem_u32(const void* p) {
    uint32_t a;
    asm("{ .reg .u64 t; cvta.to.shared.u64 t, %1; cvt.u32.u64 %0, t; }"
        : "=r"(a) : "l"(p));
    return a;
}
__device__ __forceinline__ void cp16(uint32_t dst, const void* src) {
    asm volatile("cp.async.cg.shared.global [%0], [%1], 16;"
                 :: "r"(dst), "l"(src));
}
__device__ __forceinline__ void cp16z(uint32_t dst, const void* src, int srcsz) {
    asm volatile("cp.async.cg.shared.global [%0], [%1], 16, %2;"
                 :: "r"(dst), "l"(src), "r"(srcsz));
}
__device__ __forceinline__ void mma_tf32(float* d, const uint32_t* a, const uint32_t* b) {
    asm volatile(
        "mma.sync.aligned.m16n8k8.row.col.f32.tf32.tf32.f32 "
        "{%0,%1,%2,%3}, {%4,%5,%6,%7}, {%8,%9}, {%0,%1,%2,%3};"
        : "+f"(d[0]), "+f"(d[1]), "+f"(d[2]), "+f"(d[3])
        : "r"(a[0]), "r"(a[1]), "r"(a[2]), "r"(a[3]), "r"(b[0]), "r"(b[1]));
}

// ---------------------------------------------------------------------------
__global__ void norm_x_kernel(const float* __restrict__ x) {
    int row = blockIdx.x;
    int tid = threadIdx.x;            // 128
    if (tid == 0) g_rowsum[row] = 0.0f;
    float4 v = *(const float4*)(x + (size_t)row * D_ + tid * 4);
    float ss = v.x * v.x + v.y * v.y + v.z * v.z + v.w * v.w;
    #pragma unroll
    for (int o = 16; o; o >>= 1) ss += __shfl_xor_sync(0xffffffffu, ss, o);
    __shared__ float sm[4];
    if ((tid & 31) == 0) sm[tid >> 5] = ss;
    __syncthreads();
    float inv = 1.0f / fmaxf(sqrtf(sm[0] + sm[1] + sm[2] + sm[3]), 1e-12f);
    float4 o4 = make_float4(v.x * inv, v.y * inv, v.z * inv, v.w * inv);
    *(float4*)(g_xn + (size_t)row * D_ + tid * 4) = o4;
}

// ---------------------------------------------------------------------------
__global__ void __launch_bounds__(256, 2)
arcface_gemm_kernel(const float* __restrict__ w, const int* __restrict__ target) {
    extern __shared__ __align__(16) float sm[];
    const int tid  = threadIdx.x;
    const int lane = tid & 31;
    const int wid  = tid >> 5;
    const int wm   = wid >> 2;        // 0..1 : 64-row slab
    const int wn   = wid & 3;         // 0..3 : 32-col slab
    const int gid  = lane >> 2;       // group id 0..7
    const int tig  = lane & 3;        // thread in group
    const int row0 = blockIdx.x * 128;        // input-row tile (grid.x = 4)
    const int c0   = blockIdx.y * 128;        // class tile    (grid.y = 782)

    const uint32_t sbase = smem_u32(sm);

    float acc[4][4][4];
    #pragma unroll
    for (int mi = 0; mi < 4; mi++)
        #pragma unroll
        for (int ni = 0; ni < 4; ni++)
            #pragma unroll
            for (int r = 0; r < 4; r++) acc[mi][ni][r] = 0.0f;

    // ---- async tile loader: chunk c -> stage s (A: 128x32, B: 128x32, pitch 36)
    auto load_chunk = [&](int c, int s) {
        const float* asrc = g_xn + (size_t)row0 * D_ + c * 32;
        uint32_t ab = sbase + F_AS(s) * 4;
        #pragma unroll
        for (int i = 0; i < 4; i++) {
            int g = i * 256 + tid, m = g >> 3, q = g & 7;
            cp16(ab + m * 144 + q * 16, asrc + (size_t)m * D_ + q * 4);
        }
        const float* bsrc = w + (size_t)c0 * D_ + c * 32;
        uint32_t bb = sbase + F_BS(s) * 4;
        #pragma unroll
        for (int i = 0; i < 4; i++) {
            int g = i * 256 + tid, n = g >> 3, q = g & 7;
            int sz = (c0 + n < C_) ? 16 : 0;
            cp16z(bb + n * 144 + q * 16, bsrc + (size_t)n * D_ + q * 4, sz);
        }
        asm volatile("cp.async.commit_group;" ::: "memory");
    };

    load_chunk(0, 0);
    load_chunk(1, 1);

    float ssq = 0.0f;

    for (int c = 0; c < NCHUNK; c++) {
        const int s = c & 1;
        if (c == NCHUNK - 1)
            asm volatile("cp.async.wait_group 0;" ::: "memory");
        else
            asm volatile("cp.async.wait_group 1;" ::: "memory");
        __syncthreads();

        const float* A = sm + F_AS(s);
        const float* B = sm + F_BS(s);

        // fused per-class sum(w^2) from the live B stage
        if (tid < 128) {
            const float4* bp = (const float4*)(B + tid * 36);
            #pragma unroll
            for (int q = 0; q < 8; q++) {
                float4 v = bp[q];
                ssq += v.x * v.x + v.y * v.y + v.z * v.z + v.w * v.w;
            }
        }

        #pragma unroll
        for (int kk = 0; kk < 32; kk += 8) {
            uint32_t af[4][4], bf[4][2];
            #pragma unroll
            for (int mi = 0; mi < 4; mi++) {
                int rm = wm * 64 + mi * 16 + gid;
                int kc = kk + tig;
                af[mi][0] = __float_as_uint(A[rm * 36 + kc]);
                af[mi][1] = __float_as_uint(A[(rm + 8) * 36 + kc]);
                af[mi][2] = __float_as_uint(A[rm * 36 + kc + 4]);
                af[mi][3] = __float_as_uint(A[(rm + 8) * 36 + kc + 4]);
            }
            #pragma unroll
            for (int ni = 0; ni < 4; ni++) {
                int cn = wn * 32 + ni * 8 + gid;
                bf[ni][0] = __float_as_uint(B[cn * 36 + kk + tig]);
                bf[ni][1] = __float_as_uint(B[cn * 36 + kk + 4 + tig]);
            }
            #pragma unroll
            for (int mi = 0; mi < 4; mi++)
                #pragma unroll
                for (int ni = 0; ni < 4; ni++)
                    mma_tf32(acc[mi][ni], af[mi], bf[ni]);
        }
        __syncthreads();
        if (c + 2 < NCHUNK) load_chunk(c + 2, s);
    }

    // ---- per-class inverse norms + row accumulator init
    float* wrn_s  = sm + F_WRN;
    float* rowacc = sm + F_ROW;
    if (tid < 128) {
        wrn_s[tid]  = 1.0f / fmaxf(sqrtf(ssq), 1e-12f);
        rowacc[tid] = 0.0f;
    }
    __syncthreads();

    // ---- epilogue: clip, margin on target col, fixed-shift exp partials
    #pragma unroll
    for (int mi = 0; mi < 4; mi++) {
        #pragma unroll
        for (int h = 0; h < 2; h++) {
            int r  = wm * 64 + mi * 16 + h * 8 + gid;
            int gm = row0 + r;
            int tgt = target[gm];
            float p = 0.0f;
            #pragma unroll
            for (int ni = 0; ni < 4; ni++) {
                #pragma unroll
                for (int j = 0; j < 2; j++) {
                    int lc = wn * 32 + ni * 8 + 2 * tig + j;
                    int gc = c0 + lc;
                    if (gc < C_) {
                        float cosv = acc[mi][ni][h * 2 + j] * wrn_s[lc];
                        cosv = fminf(fmaxf(cosv, CLIP_LO), CLIP_HI);
                        float logit;
                        if (gc == tgt) {
                            float t = fminf(fmaxf(1.0f - cosv * cosv, CLIP_LO), CLIP_HI);
                            float phi = cosv * COS_M_ - sqrtf(t) * SIN_M_;
                            if (!(cosv > TH_)) phi = cosv - MM_;
                            logit = phi * SCALE_;
                            g_tlogit[gm] = logit;   // one writer grid-wide
                        } else {
                            logit = cosv * SCALE_;
                        }
                        p += __expf(logit - 64.0f);
                    }
                }
            }
            p += __shfl_xor_sync(0xffffffffu, p, 1);
            p += __shfl_xor_sync(0xffffffffu, p, 2);
            if (tig == 0) atomicAdd(&rowacc[r], p);
        }
    }
    __syncthreads();
    if (tid < 128) atomicAdd(&g_rowsum[row0 + tid], rowacc[tid]);
}

// ---------------------------------------------------------------------------
__global__ void finalize_kernel(float* __restrict__ out) {
    int i = threadIdx.x;   // 512
    float v = (logf(g_rowsum[i]) + 64.0f) - g_tlogit[i];
    #pragma unroll
    for (int o = 16; o; o >>= 1) v += __shfl_xor_sync(0xffffffffu, v, o);
    __shared__ float sm[16];
    if ((i & 31) == 0) sm[i >> 5] = v;
    __syncthreads();
    if (i < 16) {
        float t = sm[i];
        #pragma unroll
        for (int o = 8; o; o >>= 1) t += __shfl_xor_sync(0x0000ffffu, t, o);
        if (i == 0) out[0] = t * (1.0f / (float)N_);
    }
}

// ---------------------------------------------------------------------------
extern "C" void kernel_launch(void* const* d_in, const int* in_sizes, int n_in,
                              void* d_out, int out_size) {
    const float* x   = (const float*)d_in[0];   // [512, 512] fp32
    const int*   tgt = (const int*)d_in[1];     // [512] int32
    const float* w   = (const float*)d_in[2];   // [100000, 512] fp32

    static int smem_set = 0;
    if (!smem_set) {
        cudaFuncSetAttribute(arcface_gemm_kernel,
                             cudaFuncAttributeMaxDynamicSharedMemorySize, SMEM_BYTES);
        smem_set = 1;
    }

    norm_x_kernel<<<N_, 128>>>(x);
    dim3 grid(4, (C_ + 127) / 128);
    arcface_gemm_kernel<<<grid, 256, SMEM_BYTES>>>(w, tgt);
    finalize_kernel<<<1, N_>>>((float*)d_out);
}

// round 5
// speedup vs baseline: 4.0825x; 1.2826x over previous
#include <cuda_runtime.h>
#include <cuda_fp16.h>
#include <math.h>
#include <stdint.h>
#include <string.h>

// ArcFace fused loss. N=512, D=512, C=100000.
//   prep_w  : w -> normalized fp16 ŵ rows in g_w16 (padded classes stay zero)
//   norm_x  : x -> normalized fp16 x̂ rows in g_x16; zero g_rowsum
//   gemm    : 128x128x512 per CTA, fp16 mma.sync.m16n8k16, 4-stage cp.async.
//             Epilogue: target col patched exactly in fp32 (clip+margin),
//             bulk softmax terms via ex2.approx.f16x2 with per-thread-row
//             integer-quantized shift; global frame 2^(K2*v - 93).
//   finalize: loss_i = log(rowsum_i) + 93*ln2 - tlogit_i; mean -> d_out[0]

#define N_ 512
#define D_ 512
#define C_ 100000
#define CPAD 100096
#define NCHUNK 16

#define CLIP_LO  (-1.0f + 1e-7f)
#define CLIP_HI  (1.0f - 1e-7f)
#define COS_M_   0.8775825618903728f
#define SIN_M_   0.4794255386042030f
#define TH_      (-0.8775825618903728f)
#define MM_      0.2397127693021015f
#define K2F      92.33248261778075f      // 64 / ln(2)
#define SHIFT_LN 64.46228625850296f      // 93 * ln(2)

// smem: 4 stages x (A 128x80B + B 128x80B) + targets + rowacc
#define SA(s)   ((s) * 20480)
#define SB(s)   ((s) * 20480 + 10240)
#define SM_TG   81920
#define SM_ROW  82432
#define SMEM_BYTES 82944

__device__ __half g_x16[N_ * D_];
__device__ __half g_w16[(size_t)CPAD * D_];   // zero-init; padded rows stay 0
__device__ float  g_rowsum[N_];
__device__ float  g_tlogit[N_];

// ------------------------------------------------------------------ helpers
__device__ __forceinline__ uint32_t smem_u32(const void* p) {
    uint32_t a;
    asm("{ .reg .u64 t; cvta.to.shared.u64 t, %1; cvt.u32.u64 %0, t; }"
        : "=r"(a) : "l"(p));
    return a;
}
__device__ __forceinline__ void cp16(uint32_t dst, const void* src) {
    asm volatile("cp.async.cg.shared.global [%0], [%1], 16;"
                 :: "r"(dst), "l"(src));
}
__device__ __forceinline__ uint32_t lds32(uint32_t a) {
    uint32_t v;
    asm volatile("ld.shared.b32 %0, [%1];" : "=r"(v) : "r"(a));
    return v;
}
__device__ __forceinline__ void mma_f16(float* d, const uint32_t* a, const uint32_t* b) {
    asm volatile(
        "mma.sync.aligned.m16n8k16.row.col.f32.f16.f16.f32 "
        "{%0,%1,%2,%3}, {%4,%5,%6,%7}, {%8,%9}, {%0,%1,%2,%3};"
        : "+f"(d[0]), "+f"(d[1]), "+f"(d[2]), "+f"(d[3])
        : "r"(a[0]), "r"(a[1]), "r"(a[2]), "r"(a[3]), "r"(b[0]), "r"(b[1]));
}
__device__ __forceinline__ uint32_t h2_bits(__half2 h) {
    uint32_t u; memcpy(&u, &h, 4); return u;
}
__device__ __forceinline__ uint32_t exp2_f16x2(float a0, float a1) {
    uint32_t hin = h2_bits(__floats2half2_rn(a0, a1));
    uint32_t d;
    asm("ex2.approx.f16x2 %0, %1;" : "=r"(d) : "r"(hin));
    return d;
}

// ---------------------------------------------------------------------------
// prep_w: one warp per class; write normalized fp16 row
// ---------------------------------------------------------------------------
__global__ void prep_w_kernel(const float* __restrict__ w) {
    int warp = (blockIdx.x * blockDim.x + threadIdx.x) >> 5;
    int lane = threadIdx.x & 31;
    if (warp >= C_) return;
    const float* p = w + (size_t)warp * D_;
    float4 v[4];
    float ss = 0.0f;
    #pragma unroll
    for (int q = 0; q < 4; q++) {
        v[q] = *(const float4*)(p + lane * 4 + q * 128);
        ss += v[q].x * v[q].x + v[q].y * v[q].y + v[q].z * v[q].z + v[q].w * v[q].w;
    }
    #pragma unroll
    for (int o = 16; o; o >>= 1) ss += __shfl_xor_sync(0xffffffffu, ss, o);
    float inv = 1.0f / fmaxf(sqrtf(ss), 1e-12f);
    uint32_t* dst = (uint32_t*)(g_w16 + (size_t)warp * D_);
    #pragma unroll
    for (int q = 0; q < 4; q++) {
        dst[lane * 2 + q * 64]     = h2_bits(__floats2half2_rn(v[q].x * inv, v[q].y * inv));
        dst[lane * 2 + 1 + q * 64] = h2_bits(__floats2half2_rn(v[q].z * inv, v[q].w * inv));
    }
}

// ---------------------------------------------------------------------------
// norm_x: normalize rows -> fp16; zero rowsums
// ---------------------------------------------------------------------------
__global__ void norm_x_kernel(const float* __restrict__ x) {
    int row = blockIdx.x;
    int tid = threadIdx.x;            // 128
    if (tid == 0) g_rowsum[row] = 0.0f;
    float4 v = *(const float4*)(x + (size_t)row * D_ + tid * 4);
    float ss = v.x * v.x + v.y * v.y + v.z * v.z + v.w * v.w;
    #pragma unroll
    for (int o = 16; o; o >>= 1) ss += __shfl_xor_sync(0xffffffffu, ss, o);
    __shared__ float sm[4];
    if ((tid & 31) == 0) sm[tid >> 5] = ss;
    __syncthreads();
    float inv = 1.0f / fmaxf(sqrtf(sm[0] + sm[1] + sm[2] + sm[3]), 1e-12f);
    uint32_t* dst = (uint32_t*)(g_x16 + (size_t)row * D_);
    dst[tid * 2]     = h2_bits(__floats2half2_rn(v.x * inv, v.y * inv));
    dst[tid * 2 + 1] = h2_bits(__floats2half2_rn(v.z * inv, v.w * inv));
}

// ---------------------------------------------------------------------------
// fused GEMM + ArcFace epilogue
// ---------------------------------------------------------------------------
__global__ void __launch_bounds__(256, 2)
arcface_gemm_kernel(const int* __restrict__ target) {
    extern __shared__ __align__(16) char smem[];
    const uint32_t sb = smem_u32(smem);
    int* tg       = (int*)(smem + SM_TG);
    float* rowacc = (float*)(smem + SM_ROW);

    const int tid  = threadIdx.x;
    const int lane = tid & 31;
    const int wid  = tid >> 5;
    const int wm   = wid >> 2;        // 64-row slab
    const int wn   = wid & 3;         // 32-col slab
    const int gid  = lane >> 2;
    const int tig  = lane & 3;
    const int row0 = blockIdx.x * 128;   // grid.x = 4
    const int c0   = blockIdx.y * 128;   // grid.y = 782

    if (tid < 128) {
        tg[tid] = target[row0 + tid];
        rowacc[tid] = 0.0f;
    }

    float acc[4][4][4];
    #pragma unroll
    for (int mi = 0; mi < 4; mi++)
        #pragma unroll
        for (int ni = 0; ni < 4; ni++)
            #pragma unroll
            for (int r = 0; r < 4; r++) acc[mi][ni][r] = 0.0f;

    auto load_chunk = [&](int c, int s) {
        const __half* asrc = g_x16 + (size_t)row0 * D_ + c * 32;
        #pragma unroll
        for (int i = 0; i < 2; i++) {
            int g = i * 256 + tid, row = g >> 2, q = g & 3;
            cp16(sb + SA(s) + row * 80 + q * 16, asrc + (size_t)row * D_ + q * 8);
        }
        const __half* bsrc = g_w16 + (size_t)c0 * D_ + c * 32;
        #pragma unroll
        for (int i = 0; i < 2; i++) {
            int g = i * 256 + tid, row = g >> 2, q = g & 3;
            cp16(sb + SB(s) + row * 80 + q * 16, bsrc + (size_t)row * D_ + q * 8);
        }
        asm volatile("cp.async.commit_group;" ::: "memory");
    };

    load_chunk(0, 0);
    load_chunk(1, 1);
    load_chunk(2, 2);

    for (int c = 0; c < NCHUNK; c++) {
        const int s = c & 3;
        asm volatile("cp.async.wait_group 2;" ::: "memory");
        __syncthreads();
        if (c + 3 < NCHUNK)
            load_chunk(c + 3, (c + 3) & 3);
        else
            asm volatile("cp.async.commit_group;" ::: "memory");  // keep group count uniform

        const uint32_t A = sb + SA(s);
        const uint32_t B = sb + SB(s);
        #pragma unroll
        for (int kk = 0; kk < 32; kk += 16) {
            uint32_t af[4][4], bf[4][2];
            #pragma unroll
            for (int mi = 0; mi < 4; mi++) {
                uint32_t off = A + (wm * 64 + mi * 16 + gid) * 80 + kk * 2 + tig * 4;
                af[mi][0] = lds32(off);
                af[mi][1] = lds32(off + 8 * 80);
                af[mi][2] = lds32(off + 16);
                af[mi][3] = lds32(off + 8 * 80 + 16);
            }
            #pragma unroll
            for (int ni = 0; ni < 4; ni++) {
                uint32_t off = B + (wn * 32 + ni * 8 + gid) * 80 + kk * 2 + tig * 4;
                bf[ni][0] = lds32(off);
                bf[ni][1] = lds32(off + 16);
            }
            #pragma unroll
            for (int mi = 0; mi < 4; mi++)
                #pragma unroll
                for (int ni = 0; ni < 4; ni++)
                    mma_f16(acc[mi][ni], af[mi], bf[ni]);
        }
    }

    // ---- epilogue -------------------------------------------------------
    #pragma unroll
    for (int mi = 0; mi < 4; mi++) {
        #pragma unroll
        for (int h = 0; h < 2; h++) {
            const int r  = wm * 64 + mi * 16 + h * 8 + gid;
            const int gm = row0 + r;
            const int lc = tg[r] - c0;

            // exact fp32 path for the target column (clip + ArcFace margin)
            if ((unsigned)lc < 128u && (lc >> 5) == wn && ((lc >> 1) & 3) == tig) {
                const int nt = (lc >> 3) & 3, j = lc & 1;
                float cv = acc[mi][nt][h * 2 + j];
                cv = fminf(fmaxf(cv, CLIP_LO), CLIP_HI);
                float t = fminf(fmaxf(1.0f - cv * cv, CLIP_LO), CLIP_HI);
                float phi = cv * COS_M_ - sqrtf(t) * SIN_M_;
                if (!(cv > TH_)) phi = cv - MM_;
                g_tlogit[gm] = phi * 64.0f;
                acc[mi][nt][h * 2 + j] = phi;   // bulk pass includes it
            }

            // bulk: integer-quantized shift, fp16x2 exp2
            float m = -0.35f;
            #pragma unroll
            for (int ni = 0; ni < 4; ni++) {
                m = fmaxf(m, acc[mi][ni][h * 2]);
                m = fmaxf(m, acc[mi][ni][h * 2 + 1]);
            }
            float Mif = ceilf(m * K2F);
            float scale = __int_as_float(((int)Mif + 34) << 23);   // 2^(Mi-93)

            uint32_t s2 = 0;
            #pragma unroll
            for (int ni = 0; ni < 4; ni++) {
                float a0 = fmaf(acc[mi][ni][h * 2],     K2F, -Mif);
                float a1 = fmaf(acc[mi][ni][h * 2 + 1], K2F, -Mif);
                uint32_t e = exp2_f16x2(a0, a1);
                asm("add.rn.f16x2 %0, %0, %1;" : "+r"(s2) : "r"(e));
            }
            __half2 sh; memcpy(&sh, &s2, 4);
            float sv = (__low2float(sh) + __high2float(sh)) * scale;
            sv += __shfl_xor_sync(0xffffffffu, sv, 1);
            sv += __shfl_xor_sync(0xffffffffu, sv, 2);
            if (tig == 0) atomicAdd(&rowacc[r], sv);
        }
    }
    __syncthreads();
    if (tid < 128) atomicAdd(&g_rowsum[row0 + tid], rowacc[tid]);
}

// ---------------------------------------------------------------------------
__global__ void finalize_kernel(float* __restrict__ out) {
    int i = threadIdx.x;   // 512
    float v = logf(g_rowsum[i]) + SHIFT_LN - g_tlogit[i];
    #pragma unroll
    for (int o = 16; o; o >>= 1) v += __shfl_xor_sync(0xffffffffu, v, o);
    __shared__ float sm[16];
    if ((i & 31) == 0) sm[i >> 5] = v;
    __syncthreads();
    if (i < 16) {
        float t = sm[i];
        #pragma unroll
        for (int o = 8; o; o >>= 1) t += __shfl_xor_sync(0x0000ffffu, t, o);
        if (i == 0) out[0] = t * (1.0f / (float)N_);
    }
}

// ---------------------------------------------------------------------------
extern "C" void kernel_launch(void* const* d_in, const int* in_sizes, int n_in,
                              void* d_out, int out_size) {
    const float* x   = (const float*)d_in[0];   // [512, 512] fp32
    const int*   tgt = (const int*)d_in[1];     // [512] int32
    const float* w   = (const float*)d_in[2];   // [100000, 512] fp32

    static int smem_set = 0;
    if (!smem_set) {
        cudaFuncSetAttribute(arcface_gemm_kernel,
                             cudaFuncAttributeMaxDynamicSharedMemorySize, SMEM_BYTES);
        smem_set = 1;
    }

    prep_w_kernel<<<(C_ + 7) / 8, 256>>>(w);
    norm_x_kernel<<<N_, 128>>>(x);
    dim3 grid(4, (C_ + 127) / 128);
    arcface_gemm_kernel<<<grid, 256, SMEM_BYTES>>>(tgt);
    finalize_kernel<<<1, N_>>>((float*)d_out);
}

// round 6
// speedup vs baseline: 4.5018x; 1.1027x over previous
#include <cuda_runtime.h>
#include <cuda_fp16.h>
#include <math.h>
#include <stdint.h>
#include <string.h>

// ArcFace fused loss. N=512, D=512, C=100000.
//   prep_w  : w -> normalized fp16 rows in g_w16 (pad classes stay zero)
//   norm_x  : x -> normalized fp16 rows scaled by 64/ln2 in g_x16 -> the GEMM
//             accumulator is the logit in log2 domain: a = 92.33*cos.
//   gemm    : 128x128x512 per CTA, mma.sync.m16n8k16 fp16 inputs + FP16
//             ACCUMULATOR (packed). Epilogue fully packed f16x2:
//             per 8-col row-chunk: max.f16x2 tree -> magic-add 1536 gives an
//             integer shift M and (bit ops only) the 2^(M-93) rescale;
//             per pair: sub.f16x2 + ex2.approx.f16x2 + add.f16x2.
//             Target column patched exactly in fp32 (clip + ArcFace margin).
//   finalize: loss_i = log(rowsum_i) + 93*ln2 - tlogit_i; mean -> d_out[0]

#define N_ 512
#define D_ 512
#define C_ 100000
#define CPAD 100096
#define NCHUNK 16

#define CLIP_LO  (-1.0f + 1e-7f)
#define CLIP_HI  (1.0f - 1e-7f)
#define COS_M_   0.8775825618903728f
#define SIN_M_   0.4794255386042030f
#define TH_      (-0.8775825618903728f)
#define MM_      0.2397127693021015f
#define K2F      92.33248261778075f      // 64 / ln(2)
#define INV_K2F  0.010830424696159f      // ln(2) / 64
#define SHIFT_LN 64.46228625850296f      // 93 * ln(2)

// smem: 4 stages x (A 128x80B + B 128x80B) + targets + rowacc
#define SA(s)   ((s) * 20480)
#define SB(s)   ((s) * 20480 + 10240)
#define SM_TG   81920
#define SM_ROW  82432
#define SMEM_BYTES 82944

__device__ __half g_x16[N_ * D_];
__device__ __half g_w16[(size_t)CPAD * D_];   // zero-init; pad rows stay 0
__device__ float  g_rowsum[N_];
__device__ float  g_tlogit[N_];

// ------------------------------------------------------------------ helpers
__device__ __forceinline__ uint32_t smem_u32(const void* p) {
    uint32_t a;
    asm("{ .reg .u64 t; cvta.to.shared.u64 t, %1; cvt.u32.u64 %0, t; }"
        : "=r"(a) : "l"(p));
    return a;
}
__device__ __forceinline__ void cp16(uint32_t dst, const void* src) {
    asm volatile("cp.async.cg.shared.global [%0], [%1], 16;"
                 :: "r"(dst), "l"(src));
}
__device__ __forceinline__ uint32_t lds32(uint32_t a) {
    uint32_t v;
    asm volatile("ld.shared.b32 %0, [%1];" : "=r"(v) : "r"(a));
    return v;
}
__device__ __forceinline__ void mma_f16acc(uint32_t* d, const uint32_t* a,
                                           const uint32_t* b) {
    asm volatile(
        "mma.sync.aligned.m16n8k16.row.col.f16.f16.f16.f16 "
        "{%0,%1}, {%2,%3,%4,%5}, {%6,%7}, {%0,%1};"
        : "+r"(d[0]), "+r"(d[1])
        : "r"(a[0]), "r"(a[1]), "r"(a[2]), "r"(a[3]), "r"(b[0]), "r"(b[1]));
}
__device__ __forceinline__ uint32_t h2_bits(__half2 h) {
    uint32_t u; memcpy(&u, &h, 4); return u;
}
__device__ __forceinline__ uint32_t hmax2(uint32_t a, uint32_t b) {
    uint32_t d;
    asm("max.f16x2 %0, %1, %2;" : "=r"(d) : "r"(a), "r"(b));
    return d;
}
__device__ __forceinline__ uint32_t hadd2(uint32_t a, uint32_t b) {
    uint32_t d;
    asm("add.rn.f16x2 %0, %1, %2;" : "=r"(d) : "r"(a), "r"(b));
    return d;
}
__device__ __forceinline__ uint32_t hsub2(uint32_t a, uint32_t b) {
    uint32_t d;
    asm("sub.rn.f16x2 %0, %1, %2;" : "=r"(d) : "r"(a), "r"(b));
    return d;
}
__device__ __forceinline__ uint32_t ex2_h2(uint32_t a) {
    uint32_t d;
    asm("ex2.approx.f16x2 %0, %1;" : "=r"(d) : "r"(a));
    return d;
}
__device__ __forceinline__ uint32_t swap16(uint32_t a) {
    uint32_t d;
    asm("prmt.b32 %0, %1, %1, 0x1032;" : "=r"(d) : "r"(a));
    return d;
}

// ---------------------------------------------------------------------------
__global__ void prep_w_kernel(const float* __restrict__ w) {
    int warp = (blockIdx.x * blockDim.x + threadIdx.x) >> 5;
    int lane = threadIdx.x & 31;
    if (warp >= C_) return;
    const float* p = w + (size_t)warp * D_;
    float4 v[4];
    float ss = 0.0f;
    #pragma unroll
    for (int q = 0; q < 4; q++) {
        v[q] = *(const float4*)(p + lane * 4 + q * 128);
        ss += v[q].x * v[q].x + v[q].y * v[q].y + v[q].z * v[q].z + v[q].w * v[q].w;
    }
    #pragma unroll
    for (int o = 16; o; o >>= 1) ss += __shfl_xor_sync(0xffffffffu, ss, o);
    float inv = 1.0f / fmaxf(sqrtf(ss), 1e-12f);
    uint32_t* dst = (uint32_t*)(g_w16 + (size_t)warp * D_);
    #pragma unroll
    for (int q = 0; q < 4; q++) {
        dst[lane * 2 + q * 64]     = h2_bits(__floats2half2_rn(v[q].x * inv, v[q].y * inv));
        dst[lane * 2 + 1 + q * 64] = h2_bits(__floats2half2_rn(v[q].z * inv, v[q].w * inv));
    }
}

// ---------------------------------------------------------------------------
__global__ void norm_x_kernel(const float* __restrict__ x) {
    int row = blockIdx.x;
    int tid = threadIdx.x;            // 128
    if (tid == 0) g_rowsum[row] = 0.0f;
    float4 v = *(const float4*)(x + (size_t)row * D_ + tid * 4);
    float ss = v.x * v.x + v.y * v.y + v.z * v.z + v.w * v.w;
    #pragma unroll
    for (int o = 16; o; o >>= 1) ss += __shfl_xor_sync(0xffffffffu, ss, o);
    __shared__ float sm[4];
    if ((tid & 31) == 0) sm[tid >> 5] = ss;
    __syncthreads();
    float inv = K2F / fmaxf(sqrtf(sm[0] + sm[1] + sm[2] + sm[3]), 1e-12f);
    uint32_t* dst = (uint32_t*)(g_x16 + (size_t)row * D_);
    dst[tid * 2]     = h2_bits(__floats2half2_rn(v.x * inv, v.y * inv));
    dst[tid * 2 + 1] = h2_bits(__floats2half2_rn(v.z * inv, v.w * inv));
}

// ---------------------------------------------------------------------------
__global__ void __launch_bounds__(256, 2)
arcface_gemm_kernel(const int* __restrict__ target) {
    extern __shared__ __align__(16) char smem[];
    const uint32_t sb = smem_u32(smem);
    int* tg       = (int*)(smem + SM_TG);
    float* rowacc = (float*)(smem + SM_ROW);

    const int tid  = threadIdx.x;
    const int lane = tid & 31;
    const int wid  = tid >> 5;
    const int wm   = wid >> 2;        // 64-row slab
    const int wn   = wid & 3;         // 32-col slab
    const int gid  = lane >> 2;
    const int tig  = lane & 3;
    const int row0 = blockIdx.x * 128;   // grid.x = 4
    const int c0   = blockIdx.y * 128;   // grid.y = 782

    if (tid < 128) {
        tg[tid] = target[row0 + tid];
        rowacc[tid] = 0.0f;
    }

    uint32_t acc[4][4][2];
    #pragma unroll
    for (int mi = 0; mi < 4; mi++)
        #pragma unroll
        for (int ni = 0; ni < 4; ni++) {
            acc[mi][ni][0] = 0u; acc[mi][ni][1] = 0u;
        }

    auto load_chunk = [&](int c, int s) {
        const __half* asrc = g_x16 + (size_t)row0 * D_ + c * 32;
        #pragma unroll
        for (int i = 0; i < 2; i++) {
            int g = i * 256 + tid, row = g >> 2, q = g & 3;
            cp16(sb + SA(s) + row * 80 + q * 16, asrc + (size_t)row * D_ + q * 8);
        }
        const __half* bsrc = g_w16 + (size_t)c0 * D_ + c * 32;
        #pragma unroll
        for (int i = 0; i < 2; i++) {
            int g = i * 256 + tid, row = g >> 2, q = g & 3;
            cp16(sb + SB(s) + row * 80 + q * 16, bsrc + (size_t)row * D_ + q * 8);
        }
        asm volatile("cp.async.commit_group;" ::: "memory");
    };

    load_chunk(0, 0);
    load_chunk(1, 1);
    load_chunk(2, 2);

    for (int c = 0; c < NCHUNK; c++) {
        const int s = c & 3;
        asm volatile("cp.async.wait_group 2;" ::: "memory");
        __syncthreads();
        if (c + 3 < NCHUNK)
            load_chunk(c + 3, (c + 3) & 3);
        else
            asm volatile("cp.async.commit_group;" ::: "memory");

        const uint32_t A = sb + SA(s);
        const uint32_t B = sb + SB(s);
        #pragma unroll
        for (int kk = 0; kk < 32; kk += 16) {
            uint32_t af[4][4], bf[4][2];
            #pragma unroll
            for (int mi = 0; mi < 4; mi++) {
                uint32_t off = A + (wm * 64 + mi * 16 + gid) * 80 + kk * 2 + tig * 4;
                af[mi][0] = lds32(off);
                af[mi][1] = lds32(off + 8 * 80);
                af[mi][2] = lds32(off + 16);
                af[mi][3] = lds32(off + 8 * 80 + 16);
            }
            #pragma unroll
            for (int ni = 0; ni < 4; ni++) {
                uint32_t off = B + (wn * 32 + ni * 8 + gid) * 80 + kk * 2 + tig * 4;
                bf[ni][0] = lds32(off);
                bf[ni][1] = lds32(off + 16);
            }
            #pragma unroll
            for (int mi = 0; mi < 4; mi++)
                #pragma unroll
                for (int ni = 0; ni < 4; ni++)
                    mma_f16acc(acc[mi][ni], af[mi], bf[ni]);
        }
    }

    // ---- epilogue (packed f16x2; acc = 92.33*cos in half2 pairs) ---------
    #pragma unroll
    for (int mi = 0; mi < 4; mi++) {
        #pragma unroll
        for (int h = 0; h < 2; h++) {
            const int r  = wm * 64 + mi * 16 + h * 8 + gid;
            const int gm = row0 + r;
            const int lc = tg[r] - c0;

            // exact fp32 path for the target column (clip + ArcFace margin)
            if ((unsigned)lc < 128u && (lc >> 5) == wn && ((lc >> 1) & 3) == tig) {
                const int nt = (lc >> 3) & 3, j = lc & 1;
                uint32_t reg = acc[mi][nt][h];
                __half2 hv; memcpy(&hv, &reg, 4);
                float av = j ? __high2float(hv) : __low2float(hv);
                float cv = av * INV_K2F;
                cv = fminf(fmaxf(cv, CLIP_LO), CLIP_HI);
                float t = fminf(fmaxf(1.0f - cv * cv, CLIP_LO), CLIP_HI);
                float phi = cv * COS_M_ - sqrtf(t) * SIN_M_;
                if (!(cv > TH_)) phi = cv - MM_;
                g_tlogit[gm] = phi * 64.0f;
                __half hp = __float2half_rn(phi * K2F);
                if (j) hv = __halves2half2(__low2half(hv), hp);
                else   hv = __halves2half2(hp, __high2half(hv));
                memcpy(&reg, &hv, 4);
                acc[mi][nt][h] = reg;
            }

            // packed chunk max over 8 columns
            uint32_t m2 = hmax2(hmax2(acc[mi][0][h], acc[mi][1][h]),
                                hmax2(acc[mi][2][h], acc[mi][3][h]));
            m2 = hmax2(m2, swap16(m2));
            // magic-add 1536 -> integer shift M (both halves) + bit-decoded
            // rescale 2^(M-93):  t = 1536+M, mant(t) = 512+M,
            // scale bits = (M + 34) << 23 = (mant - 478) << 23
            uint32_t t2 = hadd2(m2, 0x66006600u);
            uint32_t M2 = hsub2(t2, 0x66006600u);
            float scale = __int_as_float((int)((t2 & 0x3FFu) - 478u) << 23);

            uint32_t s2 = 0;
            #pragma unroll
            for (int ni = 0; ni < 4; ni++)
                s2 = hadd2(s2, ex2_h2(hsub2(acc[mi][ni][h], M2)));
            s2 = hadd2(s2, swap16(s2));
            __half2 sh; memcpy(&sh, &s2, 4);
            float p = __low2float(sh) * scale;
            p += __shfl_xor_sync(0xffffffffu, p, 1);
            p += __shfl_xor_sync(0xffffffffu, p, 2);
            if (tig == 0) atomicAdd(&rowacc[r], p);
        }
    }
    __syncthreads();
    if (tid < 128) atomicAdd(&g_rowsum[row0 + tid], rowacc[tid]);
}

// ---------------------------------------------------------------------------
__global__ void finalize_kernel(float* __restrict__ out) {
    int i = threadIdx.x;   // 512
    float v = logf(g_rowsum[i]) + SHIFT_LN - g_tlogit[i];
    #pragma unroll
    for (int o = 16; o; o >>= 1) v += __shfl_xor_sync(0xffffffffu, v, o);
    __shared__ float sm[16];
    if ((i & 31) == 0) sm[i >> 5] = v;
    __syncthreads();
    if (i < 16) {
        float t = sm[i];
        #pragma unroll
        for (int o = 8; o; o >>= 1) t += __shfl_xor_sync(0x0000ffffu, t, o);
        if (i == 0) out[0] = t * (1.0f / (float)N_);
    }
}

// ---------------------------------------------------------------------------
extern "C" void kernel_launch(void* const* d_in, const int* in_sizes, int n_in,
                              void* d_out, int out_size) {
    const float* x   = (const float*)d_in[0];   // [512, 512] fp32
    const int*   tgt = (const int*)d_in[1];     // [512] int32
    const float* w   = (const float*)d_in[2];   // [100000, 512] fp32

    static int smem_set = 0;
    if (!smem_set) {
        cudaFuncSetAttribute(arcface_gemm_kernel,
                             cudaFuncAttributeMaxDynamicSharedMemorySize, SMEM_BYTES);
        smem_set = 1;
    }

    prep_w_kernel<<<(C_ + 7) / 8, 256>>>(w);
    norm_x_kernel<<<N_, 128>>>(x);
    dim3 grid(4, (C_ + 127) / 128);
    arcface_gemm_kernel<<<grid, 256, SMEM_BYTES>>>(tgt);
    finalize_kernel<<<1, N_>>>((float*)d_out);
}

// round 8
// speedup vs baseline: 4.5458x; 1.0098x over previous
#include <cuda_runtime.h>
#include <cuda_fp16.h>
#include <math.h>
#include <stdint.h>
#include <string.h>

// ArcFace fused loss. N=512, D=512, C=100000.
//   prep    : (merged) w -> normalized fp16 rows in g_w16; x -> normalized
//             fp16 rows scaled by 64/ln2 in g_x16 (logits in log2 domain).
//   gemm    : 128x128x512 per CTA, mma.sync.m16n8k16 fp16 in / FP16 ACC.
//             Epilogue packed f16x2, per 8-col row-chunk block floating:
//             integer shift S = round(chunkmax) via magic-add; 7/8 of pairs
//             use ex2.approx.f16x2 (MUFU), 1/8 use a degree-3 FMA-pipe
//             polynomial with bit-built 2^xi (offloads the MUFU roofline).
//             Target column patched exactly in fp32 (clip + ArcFace margin).
//   finalize: loss_i = log(rowsum_i) + 93*ln2 - tlogit_i; mean -> d_out[0]

#define N_ 512
#define D_ 512
#define C_ 100000
#define CPAD 100096
#define NCHUNK 16
#define WBLOCKS 12500         // prep blocks for W: 8 classes (8 warps) each

#define CLIP_LO  (-1.0f + 1e-7f)
#define CLIP_HI  (1.0f - 1e-7f)
#define COS_M_   0.8775825618903728f
#define SIN_M_   0.4794255386042030f
#define TH_      (-0.8775825618903728f)
#define MM_      0.2397127693021015f
#define K2F      92.33248261778075f      // 64 / ln(2)
#define INV_K2F  0.010830424696159f      // ln(2) / 64
#define SHIFT_LN 64.46228625850296f      // 93 * ln(2)

// smem: 4 stages x (A 128x80B + B 128x80B) + targets + rowacc
#define SA(s)   ((s) * 20480)
#define SB(s)   ((s) * 20480 + 10240)
#define SM_TG   81920
#define SM_ROW  82432
#define SMEM_BYTES 82944

__device__ __half g_x16[N_ * D_];
__device__ __half g_w16[(size_t)CPAD * D_];   // zero-init; pad rows stay 0
__device__ float  g_rowsum[N_];
__device__ float  g_tlogit[N_];

// ------------------------------------------------------------------ helpers
__device__ __forceinline__ uint32_t smem_u32(const void* p) {
    uint32_t a;
    asm("{ .reg .u64 t; cvta.to.shared.u64 t, %1; cvt.u32.u64 %0, t; }"
        : "=r"(a) : "l"(p));
    return a;
}
__device__ __forceinline__ void cp16(uint32_t dst, const void* src) {
    asm volatile("cp.async.cg.shared.global [%0], [%1], 16;"
                 :: "r"(dst), "l"(src));
}
__device__ __forceinline__ uint32_t lds32(uint32_t a) {
    uint32_t v;
    asm volatile("ld.shared.b32 %0, [%1];" : "=r"(v) : "r"(a));
    return v;
}
__device__ __forceinline__ void mma_f16acc(uint32_t* d, const uint32_t* a,
                                           const uint32_t* b) {
    asm volatile(
        "mma.sync.aligned.m16n8k16.row.col.f16.f16.f16.f16 "
        "{%0,%1}, {%2,%3,%4,%5}, {%6,%7}, {%0,%1};"
        : "+r"(d[0]), "+r"(d[1])
        : "r"(a[0]), "r"(a[1]), "r"(a[2]), "r"(a[3]), "r"(b[0]), "r"(b[1]));
}
__device__ __forceinline__ uint32_t h2_bits(__half2 h) {
    uint32_t u; memcpy(&u, &h, 4); return u;
}
__device__ __forceinline__ uint32_t hmax2(uint32_t a, uint32_t b) {
    uint32_t d; asm("max.f16x2 %0, %1, %2;" : "=r"(d) : "r"(a), "r"(b)); return d;
}
__device__ __forceinline__ uint32_t hadd2(uint32_t a, uint32_t b) {
    uint32_t d; asm("add.rn.f16x2 %0, %1, %2;" : "=r"(d) : "r"(a), "r"(b)); return d;
}
__device__ __forceinline__ uint32_t hsub2(uint32_t a, uint32_t b) {
    uint32_t d; asm("sub.rn.f16x2 %0, %1, %2;" : "=r"(d) : "r"(a), "r"(b)); return d;
}
__device__ __forceinline__ uint32_t hmul2(uint32_t a, uint32_t b) {
    uint32_t d; asm("mul.rn.f16x2 %0, %1, %2;" : "=r"(d) : "r"(a), "r"(b)); return d;
}
__device__ __forceinline__ uint32_t hfma2_(uint32_t a, uint32_t b, uint32_t c) {
    uint32_t d; asm("fma.rn.f16x2 %0, %1, %2, %3;" : "=r"(d) : "r"(a), "r"(b), "r"(c));
    return d;
}
__device__ __forceinline__ uint32_t ex2_h2(uint32_t a) {
    uint32_t d; asm("ex2.approx.f16x2 %0, %1;" : "=r"(d) : "r"(a)); return d;
}
__device__ __forceinline__ uint32_t swap16(uint32_t a) {
    uint32_t d; asm("prmt.b32 %0, %1, %1, 0x1032;" : "=r"(d) : "r"(a)); return d;
}

// ---------------------------------------------------------------------------
// merged prep: blocks [0, WBLOCKS) normalize W classes (1 warp/class, fp16);
//              blocks [WBLOCKS, +256) normalize x rows x 92.33 -> g_x16
// ---------------------------------------------------------------------------
__global__ void prep_kernel(const float* __restrict__ w,
                            const float* __restrict__ x) {
    int b = blockIdx.x;
    if (b < WBLOCKS) {
        int warp = b * 8 + (threadIdx.x >> 5);
        int lane = threadIdx.x & 31;
        if (warp >= C_) return;
        const float* p = w + (size_t)warp * D_;
        float4 v[4];
        float ss = 0.0f;
        #pragma unroll
        for (int q = 0; q < 4; q++) {
            v[q] = *(const float4*)(p + lane * 4 + q * 128);
            ss += v[q].x * v[q].x + v[q].y * v[q].y + v[q].z * v[q].z + v[q].w * v[q].w;
        }
        #pragma unroll
        for (int o = 16; o; o >>= 1) ss += __shfl_xor_sync(0xffffffffu, ss, o);
        float inv = 1.0f / fmaxf(sqrtf(ss), 1e-12f);
        uint2* dst = (uint2*)(g_w16 + (size_t)warp * D_);
        #pragma unroll
        for (int q = 0; q < 4; q++) {
            uint2 o2;
            o2.x = h2_bits(__floats2half2_rn(v[q].x * inv, v[q].y * inv));
            o2.y = h2_bits(__floats2half2_rn(v[q].z * inv, v[q].w * inv));
            dst[lane + q * 32] = o2;
        }
    } else {
        int sub = threadIdx.x >> 7;              // 0/1 : two rows per block
        int row = (b - WBLOCKS) * 2 + sub;
        int t   = threadIdx.x & 127;
        if (t == 0) g_rowsum[row] = 0.0f;
        float4 v = *(const float4*)(x + (size_t)row * D_ + t * 4);
        float ss = v.x * v.x + v.y * v.y + v.z * v.z + v.w * v.w;
        #pragma unroll
        for (int o = 16; o; o >>= 1) ss += __shfl_xor_sync(0xffffffffu, ss, o);
        __shared__ float sm[2][4];
        if ((t & 31) == 0) sm[sub][t >> 5] = ss;
        __syncthreads();
        float inv = K2F / fmaxf(sqrtf(sm[sub][0] + sm[sub][1] + sm[sub][2] + sm[sub][3]), 1e-12f);
        uint2* dst = (uint2*)(g_x16 + (size_t)row * D_);
        uint2 o2;
        o2.x = h2_bits(__floats2half2_rn(v.x * inv, v.y * inv));
        o2.y = h2_bits(__floats2half2_rn(v.z * inv, v.w * inv));
        dst[t] = o2;
    }
}

// ---------------------------------------------------------------------------
__global__ void __launch_bounds__(256, 2)
arcface_gemm_kernel(const int* __restrict__ target) {
    extern __shared__ __align__(16) char smem[];
    const uint32_t sb = smem_u32(smem);
    int* tg       = (int*)(smem + SM_TG);
    float* rowacc = (float*)(smem + SM_ROW);

    const int tid  = threadIdx.x;
    const int lane = tid & 31;
    const int wid  = tid >> 5;
    const int wm   = wid >> 2;
    const int wn   = wid & 3;
    const int gid  = lane >> 2;
    const int tig  = lane & 3;
    const int row0 = blockIdx.x * 128;   // grid.x = 4
    const int c0   = blockIdx.y * 128;   // grid.y = 782

    if (tid < 128) {
        tg[tid] = target[row0 + tid];
        rowacc[tid] = 0.0f;
    }

    uint32_t acc[4][4][2];
    #pragma unroll
    for (int mi = 0; mi < 4; mi++)
        #pragma unroll
        for (int ni = 0; ni < 4; ni++) {
            acc[mi][ni][0] = 0u; acc[mi][ni][1] = 0u;
        }

    auto load_chunk = [&](int c, int s) {
        const __half* asrc = g_x16 + (size_t)row0 * D_ + c * 32;
        #pragma unroll
        for (int i = 0; i < 2; i++) {
            int g = i * 256 + tid, row = g >> 2, q = g & 3;
            cp16(sb + SA(s) + row * 80 + q * 16, asrc + (size_t)row * D_ + q * 8);
        }
        const __half* bsrc = g_w16 + (size_t)c0 * D_ + c * 32;
        #pragma unroll
        for (int i = 0; i < 2; i++) {
            int g = i * 256 + tid, row = g >> 2, q = g & 3;
            cp16(sb + SB(s) + row * 80 + q * 16, bsrc + (size_t)row * D_ + q * 8);
        }
        asm volatile("cp.async.commit_group;" ::: "memory");
    };

    load_chunk(0, 0);
    load_chunk(1, 1);
    load_chunk(2, 2);

    for (int c = 0; c < NCHUNK; c++) {
        const int s = c & 3;
        asm volatile("cp.async.wait_group 2;" ::: "memory");
        __syncthreads();
        if (c + 3 < NCHUNK)
            load_chunk(c + 3, (c + 3) & 3);
        else
            asm volatile("cp.async.commit_group;" ::: "memory");

        const uint32_t A = sb + SA(s);
        const uint32_t B = sb + SB(s);
        #pragma unroll
        for (int kk = 0; kk < 32; kk += 16) {
            uint32_t af[4][4], bf[4][2];
            #pragma unroll
            for (int mi = 0; mi < 4; mi++) {
                uint32_t off = A + (wm * 64 + mi * 16 + gid) * 80 + kk * 2 + tig * 4;
                af[mi][0] = lds32(off);
                af[mi][1] = lds32(off + 8 * 80);
                af[mi][2] = lds32(off + 16);
                af[mi][3] = lds32(off + 8 * 80 + 16);
            }
            #pragma unroll
            for (int ni = 0; ni < 4; ni++) {
                uint32_t off = B + (wn * 32 + ni * 8 + gid) * 80 + kk * 2 + tig * 4;
                bf[ni][0] = lds32(off);
                bf[ni][1] = lds32(off + 16);
            }
            #pragma unroll
            for (int mi = 0; mi < 4; mi++)
                #pragma unroll
                for (int ni = 0; ni < 4; ni++)
                    mma_f16acc(acc[mi][ni], af[mi], bf[ni]);
        }
    }

    // ---- epilogue (packed f16x2; acc = 92.33*cos pairs) ------------------
    #pragma unroll
    for (int mi = 0; mi < 4; mi++) {
        #pragma unroll
        for (int h = 0; h < 2; h++) {
            const int r  = wm * 64 + mi * 16 + h * 8 + gid;
            const int gm = row0 + r;
            const int lc = tg[r] - c0;

            // exact fp32 path for the target column (clip + ArcFace margin)
            if ((unsigned)lc < 128u && (lc >> 5) == wn && ((lc >> 1) & 3) == tig) {
                const int nt = (lc >> 3) & 3, j = lc & 1;
                uint32_t reg = acc[mi][nt][h];
                __half2 hv; memcpy(&hv, &reg, 4);
                float av = j ? __high2float(hv) : __low2float(hv);
                float cv = av * INV_K2F;
                cv = fminf(fmaxf(cv, CLIP_LO), CLIP_HI);
                float t = fminf(fmaxf(1.0f - cv * cv, CLIP_LO), CLIP_HI);
                float phi = cv * COS_M_ - sqrtf(t) * SIN_M_;
                if (!(cv > TH_)) phi = cv - MM_;
                g_tlogit[gm] = phi * 64.0f;
                __half hp = __float2half_rn(phi * K2F);
                if (j) hv = __halves2half2(__low2half(hv), hp);
                else   hv = __halves2half2(hp, __high2half(hv));
                memcpy(&reg, &hv, 4);
                acc[mi][nt][h] = reg;
            }

            // chunk max over 8 columns -> integer shift S via magic-add 1536
            uint32_t m2 = hmax2(hmax2(acc[mi][0][h], acc[mi][1][h]),
                                hmax2(acc[mi][2][h], acc[mi][3][h]));
            m2 = hmax2(m2, swap16(m2));
            uint32_t t2c = hadd2(m2, 0x66006600u);   // 1536 + S
            uint32_t Sv  = hsub2(t2c, 0x66006600u);  // S (exact)
            float scale  = __int_as_float((int)((t2c & 0x3FFu) - 478u) << 23); // 2^(S-93)

            uint32_t s2;
            if (h == 0) {
                // poly path for pair ni=0 (FMA/ALU pipes): p = 1/8 of pairs
                uint32_t magic2 = hsub2(0x6A006A00u, t2c);        // 1536 - S
                uint32_t clampv = hsub2(Sv, 0x4A804A80u);         // S - 13
                uint32_t ac = hmax2(acc[mi][0][h], clampv);
                uint32_t t2 = hadd2(ac, magic2);                  // 1536 + xi
                uint32_t vv = hsub2(t2, magic2);                  // xi + S
                uint32_t xf = hsub2(ac, vv);                      // [-0.5, 0.5]
                uint32_t q  = hfma2_(xf, 0x2B252B25u, 0x33AF33AFu);
                q = hfma2_(xf, q, 0x398C398Cu);
                q = hfma2_(xf, q, 0x3C003C00u);                   // 2^xf
                uint32_t su = t2 & 0x03FF03FFu;
                uint32_t sc = (su - 0x01F101F1u) << 10;           // 2^xi bits
                s2 = hmul2(q, sc);
                #pragma unroll
                for (int ni = 1; ni < 4; ni++)
                    s2 = hadd2(s2, ex2_h2(hsub2(acc[mi][ni][h], Sv)));
            } else {
                s2 = ex2_h2(hsub2(acc[mi][0][h], Sv));
                #pragma unroll
                for (int ni = 1; ni < 4; ni++)
                    s2 = hadd2(s2, ex2_h2(hsub2(acc[mi][ni][h], Sv)));
            }
            s2 = hadd2(s2, swap16(s2));
            __half2 sh; memcpy(&sh, &s2, 4);
            float p = __low2float(sh) * scale;
            p += __shfl_xor_sync(0xffffffffu, p, 1);
            p += __shfl_xor_sync(0xffffffffu, p, 2);
            if (tig == 0) atomicAdd(&rowacc[r], p);
        }
    }
    __syncthreads();
    if (tid < 128) atomicAdd(&g_rowsum[row0 + tid], rowacc[tid]);
}

// ---------------------------------------------------------------------------
__global__ void finalize_kernel(float* __restrict__ out) {
    int i = threadIdx.x;   // 512
    float v = logf(g_rowsum[i]) + SHIFT_LN - g_tlogit[i];
    #pragma unroll
    for (int o = 16; o; o >>= 1) v += __shfl_xor_sync(0xffffffffu, v, o);
    __shared__ float sm[16];
    if ((i & 31) == 0) sm[i >> 5] = v;
    __syncthreads();
    if (i < 16) {
        float t = sm[i];
        #pragma unroll
        for (int o = 8; o; o >>= 1) t += __shfl_xor_sync(0x0000ffffu, t, o);
        if (i == 0) out[0] = t * (1.0f / (float)N_);
    }
}

// ---------------------------------------------------------------------------
extern "C" void kernel_launch(void* const* d_in, const int* in_sizes, int n_in,
                              void* d_out, int out_size) {
    const float* x   = (const float*)d_in[0];   // [512, 512] fp32
    const int*   tgt = (const int*)d_in[1];     // [512] int32
    const float* w   = (const float*)d_in[2];   // [100000, 512] fp32

    static int smem_set = 0;
    if (!smem_set) {
        cudaFuncSetAttribute(arcface_gemm_kernel,
                             cudaFuncAttributeMaxDynamicSharedMemorySize, SMEM_BYTES);
        smem_set = 1;
    }

    prep_kernel<<<WBLOCKS + 256, 256>>>(w, x);
    dim3 grid(4, (C_ + 127) / 128);
    arcface_gemm_kernel<<<grid, 256, SMEM_BYTES>>>(tgt);
    finalize_kernel<<<1, N_>>>((float*)d_out);
}